// round 11
// baseline (speedup 1.0000x reference)
#include <cuda_runtime.h>
#include <math_constants.h>
#include <cstdint>

#define N_PTS 16384
#define C_DIM 64
#define K_NN  16
#define QB    128
#define DBT   64
#define NTILE (N_PTS / DBT)     // 256
#define NT    512               // 16 warps
#define STRA  64                // A row stride (floats); broadcast reads
#define STRB  66                // B row stride; 33 u64 -> half-warp conflict-free LDS.64
#define STRD  68                // dist row stride; 272B = 16B-aligned

// smem offsets (floats)
#define OFF_A   0                               // 128*64        = 8192
#define OFF_B   8192                            // 2*64*66       = 8448
#define OFF_SQ  (OFF_B + 8448)                  // 16640 ; 2*64  = 128
#define OFF_DST (OFF_SQ + 128)                  // 16768 ; 128*68 = 8704
#define OFF_TKD (OFF_DST + 8704)                // 25472 ; 16*128
#define OFF_TKI (OFF_TKD + 2048)                // 27520 ; 16*128
#define SMEM_FLOATS (OFF_TKI + 2048)            // 29568
#define SMEM_DYN (SMEM_FLOATS * 4)              // 118272 bytes

// Scratch (device globals; no dynamic allocation allowed)
__device__ float g_sq[N_PTS];
__device__ int   g_knn[N_PTS * K_NN];
__device__ float g_A[N_PTS * 256];              // x@(W1-W2)+b
__device__ float g_B[N_PTS * 256];              // x@W2

// ---------------- helpers ----------------
static __device__ __forceinline__ uint32_t smem_u32(const void* p) {
    uint32_t a;
    asm("{ .reg .u64 t; cvta.to.shared.u64 t, %1; cvt.u32.u64 %0, t; }"
        : "=r"(a) : "l"(p));
    return a;
}
static __device__ __forceinline__ void cp8(uint32_t dst, const void* src) {
    asm volatile("cp.async.ca.shared.global [%0], [%1], 8;" :: "r"(dst), "l"(src));
}
// packed fp32x2 FMA, non-volatile so ptxas can schedule
static __device__ __forceinline__ void ffma2(unsigned long long& acc,
                                             unsigned long long a,
                                             unsigned long long b) {
    asm("fma.rn.f32x2 %0, %1, %2, %0;" : "+l"(acc) : "l"(a), "l"(b));
}

// ---------------- 1) squared norms ----------------
__global__ void sqnorm_kernel(const float* __restrict__ x) {
    int i = blockIdx.x * blockDim.x + threadIdx.x;
    const float4* xr = (const float4*)(x + (long)i * C_DIM);
    float s = 0.f;
#pragma unroll
    for (int t = 0; t < C_DIM / 4; ++t) {
        float4 v = xr[t];
        s += v.x * v.x + v.y * v.y + v.z * v.z + v.w * v.w;
    }
    g_sq[i] = s;
}

// ---------------- 2) feature GEMMs: A = x@(W1-W2)+b, B = x@W2 ----------------
__global__ void feat_gemm_kernel(const float* __restrict__ x,
                                 const float* __restrict__ W,
                                 const float* __restrict__ b) {
    __shared__ float xs[16][C_DIM];
    int col = threadIdx.x;
    int row0 = blockIdx.x * 16;
    ((float4*)xs)[col] = ((const float4*)(x + (long)row0 * C_DIM))[col];
    __syncthreads();

    float p1[16], p2[16];
#pragma unroll
    for (int r = 0; r < 16; ++r) { p1[r] = 0.f; p2[r] = 0.f; }
#pragma unroll 4
    for (int c = 0; c < C_DIM; ++c) {
        float w1 = __ldg(W + c * 256 + col);
        float w2 = __ldg(W + (C_DIM + c) * 256 + col);
#pragma unroll
        for (int r = 0; r < 16; ++r) {
            float xv = xs[r][c];
            p1[r] = fmaf(xv, w1, p1[r]);
            p2[r] = fmaf(xv, w2, p2[r]);
        }
    }
    float bias = __ldg(b + col);
#pragma unroll
    for (int r = 0; r < 16; ++r) {
        g_A[(long)(row0 + r) * 256 + col] = p1[r] - p2[r] + bias;
        g_B[(long)(row0 + r) * 256 + col] = p2[r];
    }
}

// ---------------- 3) KNN: f32x2 register-blocked SGEMM -> dist tile -> scan ----------------
__global__ void __launch_bounds__(NT, 1) knn_sgemm_kernel(const float* __restrict__ x) {
    extern __shared__ float sm[];
    int tid = threadIdx.x;
    int warp = tid >> 5, lane = tid & 31;
    int qbase = blockIdx.x * QB;
    int qg = warp;                       // warp owns queries qg*8 .. qg*8+7

    // ---- A tile fill: 128q x 64k, prescaled by -2 (exact scaling) ----
#pragma unroll
    for (int it = 0; it < 4; ++it) {
        int idx = it * NT + tid;         // 2048 float4
        int q = idx >> 4, j = idx & 15;
        float4 v = ((const float4*)(x + (long)(qbase + q) * C_DIM))[j];
        v.x *= -2.f; v.y *= -2.f; v.z *= -2.f; v.w *= -2.f;
        *(float4*)&sm[OFF_A + q * STRA + j * 4] = v;
    }

    // ---- top-k state in smem, column layout (stride QB: conflict-free) ----
    if (tid < QB) {
#pragma unroll
        for (int t = 0; t < K_NN; ++t) {
            sm[OFF_TKD + t * QB + tid] = CUDART_INF_F;
            ((int*)sm)[OFF_TKI + t * QB + tid] = 0x7fffffff;
        }
    }

    // ---- B tile fill via cp.async (8B; row stride 66 floats) ----
    auto fill_b = [&](int tile, int buf) {
        int base = tile * DBT;
        uint32_t bs = smem_u32(&sm[OFF_B + buf * (DBT * STRB)]);
        const float* src = x + (long)base * C_DIM;
#pragma unroll
        for (int it = 0; it < 4; ++it) {
            int idx = it * NT + tid;     // 2048 cp8: n = idx>>5, j = idx&31
            int n = idx >> 5, j = idx & 31;
            cp8(bs + (uint32_t)(n * STRB + j * 2) * 4, src + (long)n * C_DIM + j * 2);
        }
        if (tid < 32)
            cp8(smem_u32(&sm[OFF_SQ + buf * DBT]) + tid * 8, g_sq + base + tid * 2);
    };

    fill_b(0, 0);
    asm volatile("cp.async.commit_group;" ::: "memory");
    asm volatile("cp.async.wait_group 0;" ::: "memory");
    __syncthreads();

    for (int tile = 0; tile < NTILE; ++tile) {
        int buf = tile & 1;
        int tb = tile * DBT;
        const float* bb = &sm[OFF_B + buf * (DBT * STRB)];

        // ---- compute: thread = 8q x 2db, f32x2 packed over k (acc = 32 regs) ----
        unsigned long long acc[8][2];
#pragma unroll
        for (int i = 0; i < 8; ++i) { acc[i][0] = 0ull; acc[i][1] = 0ull; }

#pragma unroll
        for (int kk = 0; kk < C_DIM / 4; ++kk) {
            unsigned long long b0[2], b1[2];
#pragma unroll
            for (int m = 0; m < 2; ++m) {
                const float* bp = bb + (lane + 32 * m) * STRB + kk * 4;
                b0[m] = *(const unsigned long long*)(bp);
                b1[m] = *(const unsigned long long*)(bp + 2);
            }
#pragma unroll
            for (int qh = 0; qh < 2; ++qh) {
                unsigned long long ax[4], ay[4];
#pragma unroll
                for (int i = 0; i < 4; ++i) {
                    const float* ap = &sm[OFF_A + (qg * 8 + qh * 4 + i) * STRA + kk * 4];
                    ax[i] = *(const unsigned long long*)(ap);
                    ay[i] = *(const unsigned long long*)(ap + 2);
                }
#pragma unroll
                for (int i = 0; i < 4; ++i) {
                    ffma2(acc[qh * 4 + i][0], ax[i], b0[0]);
                    ffma2(acc[qh * 4 + i][1], ax[i], b0[1]);
                }
#pragma unroll
                for (int i = 0; i < 4; ++i) {
                    ffma2(acc[qh * 4 + i][0], ay[i], b1[0]);
                    ffma2(acc[qh * 4 + i][1], ay[i], b1[1]);
                }
            }
        }

        // ---- prefetch next B tile (overlaps epilogue + scan) ----
        if (tile + 1 < NTILE) {
            fill_b(tile + 1, buf ^ 1);
            asm volatile("cp.async.commit_group;" ::: "memory");
        }

        // ---- epilogue: d = sum2(acc) + |p|^2 (query norm dropped) ----
        {
            float sq0 = sm[OFF_SQ + buf * DBT + lane];
            float sq1 = sm[OFF_SQ + buf * DBT + lane + 32];
#pragma unroll
            for (int i = 0; i < 8; ++i) {
                float lo0 = __uint_as_float((uint32_t)acc[i][0]);
                float hi0 = __uint_as_float((uint32_t)(acc[i][0] >> 32));
                float lo1 = __uint_as_float((uint32_t)acc[i][1]);
                float hi1 = __uint_as_float((uint32_t)(acc[i][1] >> 32));
                sm[OFF_DST + (qg * 8 + i) * STRD + lane]      = lo0 + hi0 + sq0;
                sm[OFF_DST + (qg * 8 + i) * STRD + lane + 32] = lo1 + hi1 + sq1;
            }
        }
        __syncthreads();   // dist tile ready

        // ---- scan: threads 0..127, one query each; top-k in smem ----
        if (tid < QB) {
            int q = qbase + tid;
            int self = q - tb;
            if ((unsigned)self < (unsigned)DBT)
                sm[OFF_DST + tid * STRD + self] = CUDART_INF_F;
            float* kds = &sm[OFF_TKD + tid];
            int* kis = ((int*)sm) + OFF_TKI + tid;
            float thr = kds[15 * QB];
            int thi = kis[15 * QB];
            const float* row = &sm[OFF_DST + tid * STRD];
#pragma unroll 4
            for (int j = 0; j < DBT / 4; ++j) {
                float4 dv = *(const float4*)(row + 4 * j);
                float mn = fminf(fminf(dv.x, dv.y), fminf(dv.z, dv.w));
                if (mn <= thr) {
                    float ds[4] = {dv.x, dv.y, dv.z, dv.w};
#pragma unroll
                    for (int e = 0; e < 4; ++e) {
                        float d = ds[e];
                        int col = tb + 4 * j + e;
                        if (d < thr || (d == thr && col < thi)) {
                            // smem insertion sort (cold path)
                            kds[15 * QB] = d; kis[15 * QB] = col;
#pragma unroll
                            for (int t = K_NN - 1; t > 0; --t) {
                                float da = kds[t * QB], db_ = kds[(t - 1) * QB];
                                int ia = kis[t * QB], ib = kis[(t - 1) * QB];
                                if (da < db_ || (da == db_ && ia < ib)) {
                                    kds[t * QB] = db_; kds[(t - 1) * QB] = da;
                                    kis[t * QB] = ib;  kis[(t - 1) * QB] = ia;
                                }
                            }
                            thr = kds[15 * QB];
                            thi = kis[15 * QB];
                        }
                    }
                }
            }
        }
        asm volatile("cp.async.wait_group 0;" ::: "memory");
        __syncthreads();   // next B buf ready + dist free
    }

    if (tid < QB) {
        int q = qbase + tid;
#pragma unroll
        for (int t = 0; t < K_NN; ++t)
            g_knn[(long)q * K_NN + t] = ((int*)sm)[OFF_TKI + t * QB + tid];
    }
}

// ---------------- 4) gather + max + relu + pixel-shuffle scatter ----------------
__global__ void gather_max_kernel(float* __restrict__ y) {
    int t = threadIdx.x;
    int q = blockIdx.x * 4 + (t >> 6);
    int c = t & 63;
    const int* idx = g_knn + (long)q * K_NN;
    const float4* Bv = (const float4*)g_B;
    float4 m = make_float4(-CUDART_INF_F, -CUDART_INF_F, -CUDART_INF_F, -CUDART_INF_F);
#pragma unroll
    for (int k = 0; k < K_NN; ++k) {
        int j = __ldg(idx + k);
        float4 bv = Bv[(long)j * 64 + c];
        m.x = fmaxf(m.x, bv.x); m.y = fmaxf(m.y, bv.y);
        m.z = fmaxf(m.z, bv.z); m.w = fmaxf(m.w, bv.w);
    }
    float4 a = ((const float4*)g_A)[(long)q * 64 + c];
    y[((long)q * 4 + 0) * 64 + c] = fmaxf(a.x + m.x, 0.f);
    y[((long)q * 4 + 1) * 64 + c] = fmaxf(a.y + m.y, 0.f);
    y[((long)q * 4 + 2) * 64 + c] = fmaxf(a.z + m.z, 0.f);
    y[((long)q * 4 + 3) * 64 + c] = fmaxf(a.w + m.w, 0.f);
}

extern "C" void kernel_launch(void* const* d_in, const int* in_sizes, int n_in,
                              void* d_out, int out_size) {
    const float* x = (const float*)d_in[0];   // (16384, 64) f32
    const float* W = (const float*)d_in[1];   // (128, 256) f32
    const float* b = (const float*)d_in[2];   // (256,) f32
    float* y = (float*)d_out;                 // (65536, 64) f32

    cudaFuncSetAttribute(knn_sgemm_kernel,
                         cudaFuncAttributeMaxDynamicSharedMemorySize, SMEM_DYN);

    sqnorm_kernel<<<N_PTS / 256, 256>>>(x);
    feat_gemm_kernel<<<N_PTS / 16, 256>>>(x, W, b);
    knn_sgemm_kernel<<<N_PTS / QB, NT, SMEM_DYN>>>(x);
    gather_max_kernel<<<N_PTS / 4, 256>>>(y);
}